// round 8
// baseline (speedup 1.0000x reference)
#include <cuda_runtime.h>
#include <cstdint>

// ---------------- problem constants ----------------
#define B_    8
#define CIN   128
#define COUT  128
#define NPTS  8192
#define KM    32
#define MODES 256
#define SPLIT1 16
#define KC    64          // K per chunk (fp32 elems)
#define NT_   128         // N tile
#define NTHR  512
#define IGRP  8           // i-groups for stage-2 split

// ---------------- device scratch ----------------
__device__ float g_part[SPLIT1 * B_ * CIN * MODES];   // 16.8 MB
__device__ float g_xhat[B_ * CIN * MODES];            // 1 MB
__device__ float g_W2[CIN * COUT * MODES];            // 16.8 MB
__device__ float g_part2[IGRP * B_ * COUT * MODES];   // 8.4 MB
__device__ float g_yhat[B_ * COUT * MODES];           // 1 MB

__device__ __forceinline__ uint32_t smem_u32(const void* p) {
    uint32_t a;
    asm("{ .reg .u64 t; cvta.to.shared.u64 t, %1; cvt.u32.u64 %0, t; }" : "=r"(a) : "l"(p));
    return a;
}
__device__ __forceinline__ uint32_t pk_bf16(float lo, float hi) {
    uint32_t r;
    asm("cvt.rn.bf16x2.f32 %0, %1, %2;" : "=r"(r) : "f"(hi), "f"(lo));
    return r;
}
// convert 8 consecutive fp32 to hi/lo bf16, store 16B each at hiA/loA
__device__ __forceinline__ void cvt_store8(uint32_t hiA, uint32_t loA, float4 v0, float4 v1) {
    uint32_t h0 = pk_bf16(v0.x, v0.y);
    uint32_t h1 = pk_bf16(v0.z, v0.w);
    uint32_t h2 = pk_bf16(v1.x, v1.y);
    uint32_t h3 = pk_bf16(v1.z, v1.w);
    float r0 = v0.x - __uint_as_float(h0 << 16);
    float r1 = v0.y - __uint_as_float(h0 & 0xffff0000u);
    float r2 = v0.z - __uint_as_float(h1 << 16);
    float r3 = v0.w - __uint_as_float(h1 & 0xffff0000u);
    float r4 = v1.x - __uint_as_float(h2 << 16);
    float r5 = v1.y - __uint_as_float(h2 & 0xffff0000u);
    float r6 = v1.z - __uint_as_float(h3 << 16);
    float r7 = v1.w - __uint_as_float(h3 & 0xffff0000u);
    uint32_t l0 = pk_bf16(r0, r1), l1 = pk_bf16(r2, r3);
    uint32_t l2 = pk_bf16(r4, r5), l3 = pk_bf16(r6, r7);
    asm volatile("st.shared.v4.b32 [%0], {%1,%2,%3,%4};" :: "r"(hiA), "r"(h0), "r"(h1), "r"(h2), "r"(h3));
    asm volatile("st.shared.v4.b32 [%0], {%1,%2,%3,%4};" :: "r"(loA), "r"(l0), "r"(l1), "r"(l2), "r"(l3));
}

#define LDSM4(r, addr) \
    asm volatile("ldmatrix.sync.aligned.m8n8.x4.shared.b16 {%0,%1,%2,%3}, [%4];" \
        : "=r"((r)[0]), "=r"((r)[1]), "=r"((r)[2]), "=r"((r)[3]) : "r"(addr))
#define LDSM4T(r, addr) \
    asm volatile("ldmatrix.sync.aligned.m8n8.x4.trans.shared.b16 {%0,%1,%2,%3}, [%4];" \
        : "=r"((r)[0]), "=r"((r)[1]), "=r"((r)[2]), "=r"((r)[3]) : "r"(addr))
#define MMA(c, a, bq) \
    asm volatile("mma.sync.aligned.m16n8k16.row.col.f32.bf16.bf16.f32 " \
        "{%0,%1,%2,%3}, {%4,%5,%6,%7}, {%8,%9}, {%0,%1,%2,%3};" \
        : "+f"((c)[0]), "+f"((c)[1]), "+f"((c)[2]), "+f"((c)[3]) \
        : "r"((a)[0]), "r"((a)[1]), "r"((a)[2]), "r"((a)[3]), "r"((bq)[0]), "r"((bq)[1]))

// ===========================================================================
// GEMM variant NT (stage 3): fragment-pipelined (ahi/bhi double-buffered).
// ===========================================================================
#define RSTR   144
#define ABYT   (128 * RSTR)                    // 18432
#define NT_OFF_AH 0
#define NT_OFF_AL (ABYT)
#define NT_OFF_BH (2 * ABYT)
#define NT_OFF_BL (3 * ABYT)
#define NT_STAGE  (4 * ABYT)                   // 73728
#define NT_SMEM   (2 * NT_STAGE)               // 147456

__global__ __launch_bounds__(NTHR, 1) void gemm_nt(
    const float* __restrict__ A, const float* __restrict__ B, float* __restrict__ C,
    int lda, int ldb, int ldc,
    long sA, long sB, long sCb, int nChunks)
{
    extern __shared__ __align__(16) char smem[];
    const uint32_t sb = smem_u32(smem);
    const int tid = threadIdx.x, wid = tid >> 5, lane = tid & 31;
    const int nt = blockIdx.x, b = blockIdx.z;

    const float* Ab = A + (long)b * sA;
    const float* Bb = B + (long)b * sB + (long)nt * NT_ * ldb;
    float* Cb = C + (long)b * sCb + (long)nt * NT_;

    const int srow = tid >> 2, sk = (tid & 3) * 16;
    const float* ag = Ab + (long)srow * lda + sk;
    const float* bg = Bb + (long)srow * ldb + sk;
    const uint32_t sOff = (uint32_t)(srow * RSTR + sk * 2);

    const int wm = wid >> 2, wn = wid & 3;
    const int l16 = lane & 15, lh = lane >> 4;
    const int bn = ((lane >> 4) & 1) * 8 + (lane & 7);
    const int bk = ((lane >> 3) & 1) * 8;

    float c[2][4][4];
#pragma unroll
    for (int i = 0; i < 2; i++)
#pragma unroll
        for (int j = 0; j < 4; j++)
#pragma unroll
            for (int q = 0; q < 4; q++) c[i][j][q] = 0.f;

    float4 bv[4];

    // prologue: chunk 0 -> buffer 0 (A loaded inline; B via bv)
    {
        float4 a0 = *(const float4*)(ag),     a1 = *(const float4*)(ag + 4);
        float4 a2 = *(const float4*)(ag + 8), a3 = *(const float4*)(ag + 12);
        bv[0] = *(const float4*)(bg);     bv[1] = *(const float4*)(bg + 4);
        bv[2] = *(const float4*)(bg + 8); bv[3] = *(const float4*)(bg + 12);
        cvt_store8(sb + NT_OFF_AH + sOff,      sb + NT_OFF_AL + sOff,      a0, a1);
        cvt_store8(sb + NT_OFF_AH + sOff + 16, sb + NT_OFF_AL + sOff + 16, a2, a3);
        cvt_store8(sb + NT_OFF_BH + sOff,      sb + NT_OFF_BL + sOff,      bv[0], bv[1]);
        cvt_store8(sb + NT_OFF_BH + sOff + 16, sb + NT_OFF_BL + sOff + 16, bv[2], bv[3]);
    }

    for (int i = 0; i < nChunks; i++) {
        __syncthreads();
        const int cur = i & 1;
        const bool more = (i + 1 < nChunks);
        if (more) {
            const float* bg2 = bg + (long)(i + 1) * KC;
            bv[0] = *(const float4*)(bg2);     bv[1] = *(const float4*)(bg2 + 4);
            bv[2] = *(const float4*)(bg2 + 8); bv[3] = *(const float4*)(bg2 + 12);
        }
        const uint32_t base = sb + (uint32_t)(cur * NT_STAGE);
        const uint32_t aBase = base + NT_OFF_AH + (uint32_t)((wm * 32 + l16) * RSTR + lh * 16);
        const uint32_t bBase = base + NT_OFF_BH + (uint32_t)((wn * 32 + bn) * RSTR + bk * 2);

        uint32_t ahi[2][8], bhi[2][8], alo[8], blo[8];
        // chunk prologue: h=0 hi fragments
        LDSM4(&ahi[0][0], aBase);
        LDSM4(&ahi[0][4], aBase + 16 * RSTR);
        LDSM4(&bhi[0][0], bBase);
        LDSM4(&bhi[0][4], bBase + 16 * RSTR);
#pragma unroll
        for (int h = 0; h < 4; h++) {
            const int pb = h & 1;
            const uint32_t aA = aBase + h * 32, bA = bBase + h * 32;
            // lo fragments for this h (hidden by hi MMAs below)
            LDSM4(&alo[0], aA + ABYT);
            LDSM4(&alo[4], aA + ABYT + 16 * RSTR);
            LDSM4(&blo[0], bA + ABYT);
            LDSM4(&blo[4], bA + ABYT + 16 * RSTR);
            if (h < 3) {  // next-h hi fragments
                LDSM4(&ahi[pb ^ 1][0], aA + 32);
                LDSM4(&ahi[pb ^ 1][4], aA + 32 + 16 * RSTR);
                LDSM4(&bhi[pb ^ 1][0], bA + 32);
                LDSM4(&bhi[pb ^ 1][4], bA + 32 + 16 * RSTR);
            }
#pragma unroll
            for (int mt = 0; mt < 2; mt++)
#pragma unroll
                for (int nn = 0; nn < 4; nn++)
                    MMA(c[mt][nn], &ahi[pb][mt * 4], &bhi[pb][nn * 2]);
#pragma unroll
            for (int mt = 0; mt < 2; mt++)
#pragma unroll
                for (int nn = 0; nn < 4; nn++)
                    MMA(c[mt][nn], &alo[mt * 4], &bhi[pb][nn * 2]);
#pragma unroll
            for (int mt = 0; mt < 2; mt++)
#pragma unroll
                for (int nn = 0; nn < 4; nn++)
                    MMA(c[mt][nn], &ahi[pb][mt * 4], &blo[nn * 2]);
        }
        if (more) {
            const uint32_t nb = sb + (uint32_t)(((i + 1) & 1) * NT_STAGE);
            const float* ag2 = ag + (long)(i + 1) * KC;
            float4 a0 = *(const float4*)(ag2),     a1 = *(const float4*)(ag2 + 4);
            float4 a2 = *(const float4*)(ag2 + 8), a3 = *(const float4*)(ag2 + 12);
            cvt_store8(nb + NT_OFF_AH + sOff,      nb + NT_OFF_AL + sOff,      a0, a1);
            cvt_store8(nb + NT_OFF_AH + sOff + 16, nb + NT_OFF_AL + sOff + 16, a2, a3);
            cvt_store8(nb + NT_OFF_BH + sOff,      nb + NT_OFF_BL + sOff,      bv[0], bv[1]);
            cvt_store8(nb + NT_OFF_BH + sOff + 16, nb + NT_OFF_BL + sOff + 16, bv[2], bv[3]);
        }
    }

    const int mrow = wm * 32 + (lane >> 2);
    const int ncol = wn * 32 + (lane & 3) * 2;
#pragma unroll
    for (int mt = 0; mt < 2; mt++)
#pragma unroll
        for (int nn = 0; nn < 4; nn++) {
            float* p = Cb + (long)(mrow + mt * 16) * ldc + ncol + nn * 8;
            *(float2*)p = make_float2(c[mt][nn][0], c[mt][nn][1]);
            *(float2*)(p + (long)8 * ldc) = make_float2(c[mt][nn][2], c[mt][nn][3]);
        }
}

// ===========================================================================
// GEMM variant TB (stage 1): LDSM hoisted to h-start (blo gets own regs).
// ===========================================================================
#define BRSTR  272                              // 128 modes*2B + 16B pad
#define TB_ABYT (128 * RSTR)                    // 18432 per A half
#define TB_BBYT (KC * BRSTR)                    // 17408 per B half
#define TB_OFF_AH 0
#define TB_OFF_AL (TB_ABYT)
#define TB_OFF_BH (2 * TB_ABYT)
#define TB_OFF_BL (2 * TB_ABYT + TB_BBYT)
#define TB_STAGE  (2 * TB_ABYT + 2 * TB_BBYT)   // 71680
#define TB_SMEM   (2 * TB_STAGE)                // 143360

__global__ __launch_bounds__(NTHR, 1) void gemm_tb(
    const float* __restrict__ A, const float* __restrict__ B, float* __restrict__ C,
    int nChunks)
{
    extern __shared__ __align__(16) char smem[];
    const uint32_t sb = smem_u32(smem);
    const int tid = threadIdx.x, wid = tid >> 5, lane = tid & 31;
    const int nt = blockIdx.x, sp = blockIdx.y, b = blockIdx.z;
    const long k0 = (long)sp * nChunks * KC;

    const float* Ab = A + (long)b * CIN * NPTS + k0;
    const float* Bb = B + (long)b * NPTS * MODES + k0 * MODES + nt * NT_;
    float* Cb = C + ((long)sp * B_ + b) * CIN * MODES + nt * NT_;

    const int srow = tid >> 2, sk = (tid & 3) * 16;
    const float* ag = Ab + (long)srow * NPTS + sk;
    const uint32_t aOff = (uint32_t)(srow * RSTR + sk * 2);
    const int brow = tid >> 4, bc = (tid & 15) * 8;
    const float* bg = Bb + (long)brow * MODES + bc;
    const uint32_t bOff = (uint32_t)(brow * BRSTR + bc * 2);

    const int wm = wid >> 2, wn = wid & 3;
    const int l16 = lane & 15, lh = lane >> 4;
    const int tkl = ((lane >> 3) & 1) * 8 + (lane & 7);
    const int tnl = (lane >> 4) * 8;

    float c[2][4][4];
#pragma unroll
    for (int i = 0; i < 2; i++)
#pragma unroll
        for (int j = 0; j < 4; j++)
#pragma unroll
            for (int q = 0; q < 4; q++) c[i][j][q] = 0.f;

    float4 bv[4];
    {
        float4 a0 = *(const float4*)(ag),     a1 = *(const float4*)(ag + 4);
        float4 a2 = *(const float4*)(ag + 8), a3 = *(const float4*)(ag + 12);
        bv[0] = *(const float4*)(bg);
        bv[1] = *(const float4*)(bg + 4);
        bv[2] = *(const float4*)(bg + (long)32 * MODES);
        bv[3] = *(const float4*)(bg + (long)32 * MODES + 4);
        cvt_store8(sb + TB_OFF_AH + aOff,      sb + TB_OFF_AL + aOff,      a0, a1);
        cvt_store8(sb + TB_OFF_AH + aOff + 16, sb + TB_OFF_AL + aOff + 16, a2, a3);
        cvt_store8(sb + TB_OFF_BH + bOff,      sb + TB_OFF_BL + bOff,      bv[0], bv[1]);
        cvt_store8(sb + TB_OFF_BH + bOff + 32 * BRSTR, sb + TB_OFF_BL + bOff + 32 * BRSTR, bv[2], bv[3]);
    }

    for (int i = 0; i < nChunks; i++) {
        __syncthreads();
        const int cur = i & 1;
        const bool more = (i + 1 < nChunks);
        if (more) {
            const float* bg2 = bg + (long)(i + 1) * KC * MODES;
            bv[0] = *(const float4*)(bg2);
            bv[1] = *(const float4*)(bg2 + 4);
            bv[2] = *(const float4*)(bg2 + (long)32 * MODES);
            bv[3] = *(const float4*)(bg2 + (long)32 * MODES + 4);
        }
        const uint32_t base = sb + (uint32_t)(cur * TB_STAGE);
#pragma unroll
        for (int h = 0; h < 4; h++) {
            uint32_t ahi[8], alo[8], bhi[8], blo[8];
            const uint32_t aAddr = base + TB_OFF_AH + (uint32_t)((wm * 32 + l16) * RSTR + (h * 16 + lh * 8) * 2);
            const uint32_t bAddr = base + TB_OFF_BH + (uint32_t)((h * 16 + tkl) * BRSTR + (wn * 32 + tnl) * 2);
            // all fragment loads issued up-front; blo/alo stalls hidden by MMAs
            LDSM4(&ahi[0], aAddr);
            LDSM4(&ahi[4], aAddr + 16 * RSTR);
            LDSM4T(&bhi[0], bAddr);
            LDSM4T(&bhi[4], bAddr + 16 * 2);
            LDSM4(&alo[0], aAddr + TB_ABYT);
            LDSM4(&alo[4], aAddr + TB_ABYT + 16 * RSTR);
            LDSM4T(&blo[0], bAddr + TB_BBYT);
            LDSM4T(&blo[4], bAddr + TB_BBYT + 16 * 2);
#pragma unroll
            for (int mt = 0; mt < 2; mt++)
#pragma unroll
                for (int nn = 0; nn < 4; nn++)
                    MMA(c[mt][nn], &ahi[mt * 4], &bhi[nn * 2]);
#pragma unroll
            for (int mt = 0; mt < 2; mt++)
#pragma unroll
                for (int nn = 0; nn < 4; nn++)
                    MMA(c[mt][nn], &alo[mt * 4], &bhi[nn * 2]);
#pragma unroll
            for (int mt = 0; mt < 2; mt++)
#pragma unroll
                for (int nn = 0; nn < 4; nn++)
                    MMA(c[mt][nn], &ahi[mt * 4], &blo[nn * 2]);
        }
        if (more) {
            const uint32_t nb = sb + (uint32_t)(((i + 1) & 1) * TB_STAGE);
            const float* ag2 = ag + (long)(i + 1) * KC;
            float4 a0 = *(const float4*)(ag2),     a1 = *(const float4*)(ag2 + 4);
            float4 a2 = *(const float4*)(ag2 + 8), a3 = *(const float4*)(ag2 + 12);
            cvt_store8(nb + TB_OFF_AH + aOff,      nb + TB_OFF_AL + aOff,      a0, a1);
            cvt_store8(nb + TB_OFF_AH + aOff + 16, nb + TB_OFF_AL + aOff + 16, a2, a3);
            cvt_store8(nb + TB_OFF_BH + bOff,      nb + TB_OFF_BL + bOff,      bv[0], bv[1]);
            cvt_store8(nb + TB_OFF_BH + bOff + 32 * BRSTR, nb + TB_OFF_BL + bOff + 32 * BRSTR, bv[2], bv[3]);
        }
    }

    const int mrow = wm * 32 + (lane >> 2);
    const int ncol = wn * 32 + (lane & 3) * 2;
#pragma unroll
    for (int mt = 0; mt < 2; mt++)
#pragma unroll
        for (int nn = 0; nn < 4; nn++) {
            float* p = Cb + (long)(mrow + mt * 16) * MODES + ncol + nn * 8;
            *(float2*)p = make_float2(c[mt][nn][0], c[mt][nn][1]);
            *(float2*)(p + (long)8 * MODES) = make_float2(c[mt][nn][2], c[mt][nn][3]);
        }
}

// W2[r,k] = sum_j weights[r,j] * D[j,k]
__global__ __launch_bounds__(256) void k2a_w2(const float* __restrict__ weights,
                                              const float* __restrict__ D) {
    __shared__ float ws[64][KM];
    const int r0 = blockIdx.x * 64;
    const int k  = threadIdx.x;
    for (int idx = threadIdx.x; idx < 64 * KM; idx += 256)
        ws[idx >> 5][idx & 31] = weights[(size_t)r0 * KM + idx];
    float Dreg[KM];
#pragma unroll
    for (int j = 0; j < KM; j++) Dreg[j] = D[(size_t)j * MODES + k];
    __syncthreads();
    for (int r = 0; r < 64; r++) {
        float acc = 0.f;
#pragma unroll
        for (int j = 0; j < KM; j++) acc += ws[r][j] * Dreg[j];
        g_W2[(size_t)(r0 + r) * MODES + k] = acc;
    }
}

// split-K reduce: x_hat = sum over SPLIT1 partials (float4, coalesced)
__global__ __launch_bounds__(256) void k1_reduce() {
    const int i = blockIdx.x * 256 + threadIdx.x;
    const float4* p = (const float4*)g_part;
    float4 s = p[i];
#pragma unroll
    for (int q = 1; q < SPLIT1; q++) {
        float4 v = p[(size_t)q * (B_ * CIN * MODES / 4) + i];
        s.x += v.x; s.y += v.y; s.z += v.z; s.w += v.w;
    }
    ((float4*)g_xhat)[i] = s;
}

// Stage-2 partial: grid (32 o-tiles, IGRP, 4 b-pairs). 2 batches per block.
__global__ __launch_bounds__(256) void k2b_part() {
    const int o0 = blockIdx.x * 4;
    const int g  = blockIdx.y;
    const int b0 = blockIdx.z * 2;
    const int k  = threadIdx.x;
    float acc[2][4];
#pragma unroll
    for (int b = 0; b < 2; b++)
#pragma unroll
        for (int oo = 0; oo < 4; oo++) acc[b][oo] = 0.f;
    const int i0 = g * (CIN / IGRP);
#pragma unroll
    for (int ii = 0; ii < CIN / IGRP; ii++) {
        const int i = i0 + ii;
        float w[4];
#pragma unroll
        for (int oo = 0; oo < 4; oo++)
            w[oo] = g_W2[((size_t)i * COUT + o0 + oo) * MODES + k];
#pragma unroll
        for (int b = 0; b < 2; b++) {
            const float xv = g_xhat[((size_t)(b0 + b) * CIN + i) * MODES + k];
#pragma unroll
            for (int oo = 0; oo < 4; oo++) acc[b][oo] += xv * w[oo];
        }
    }
#pragma unroll
    for (int b = 0; b < 2; b++)
#pragma unroll
        for (int oo = 0; oo < 4; oo++)
            g_part2[(((size_t)g * B_ + b0 + b) * COUT + o0 + oo) * MODES + k] = acc[b][oo];
}

// Final stage-2 reduce: yhat = sum over IGRP groups (float4, coalesced)
__global__ __launch_bounds__(256) void k2b_red2() {
    const int i = blockIdx.x * 256 + threadIdx.x;
    const float4* p = (const float4*)g_part2;
    float4 s = p[i];
#pragma unroll
    for (int q = 1; q < IGRP; q++) {
        float4 v = p[(size_t)q * (B_ * COUT * MODES / 4) + i];
        s.x += v.x; s.y += v.y; s.z += v.z; s.w += v.w;
    }
    ((float4*)g_yhat)[i] = s;
}

// ---------------------------------------------------------------------------
extern "C" void kernel_launch(void* const* d_in, const int* in_sizes, int n_in,
                              void* d_out, int out_size) {
    const float* x       = (const float*)d_in[0];   // (8, 128, 8192)
    const float* wbases  = (const float*)d_in[1];   // (8, 8192, 256)
    const float* bases   = (const float*)d_in[2];   // (8, 8192, 256)
    const float* weights = (const float*)d_in[3];   // (128, 128, 32)
    const float* Dm      = (const float*)d_in[4];   // (32, 256)
    float* y = (float*)d_out;                       // (8, 128, 8192)

    cudaFuncSetAttribute(gemm_nt, cudaFuncAttributeMaxDynamicSharedMemorySize, NT_SMEM);
    cudaFuncSetAttribute(gemm_tb, cudaFuncAttributeMaxDynamicSharedMemorySize, TB_SMEM);

    void *p_part, *p_yhat;
    cudaGetSymbolAddress(&p_part, g_part);
    cudaGetSymbolAddress(&p_yhat, g_yhat);

    // (1) W2 precompute
    k2a_w2<<<CIN * COUT / 64, 256>>>(weights, Dm);

    // (2) Stage 1: x_hat partials = x @ wbases
    gemm_tb<<<dim3(MODES / NT_, SPLIT1, B_), NTHR, TB_SMEM>>>(
        x, wbases, (float*)p_part, (NPTS / SPLIT1) / KC);   // 8 chunks

    // (3) split-K reduce
    k1_reduce<<<(B_ * CIN * MODES / 4) / 256, 256>>>();

    // (4) stage-2 partials (1024 CTAs)
    k2b_part<<<dim3(COUT / 4, IGRP, 4), 256>>>();

    // (5) stage-2 final reduce
    k2b_red2<<<(B_ * COUT * MODES / 4) / 256, 256>>>();

    // (6) Stage 3: y = y_hat @ bases^T
    gemm_nt<<<dim3(NPTS / NT_, 1, B_), NTHR, NT_SMEM>>>(
        (const float*)p_yhat, bases, y,
        MODES, MODES, NPTS,
        (long)COUT * MODES, (long)NPTS * MODES, (long)CIN * NPTS,
        MODES / KC);                                        // 4 chunks
}

// round 9
// speedup vs baseline: 1.2029x; 1.2029x over previous
#include <cuda_runtime.h>
#include <cstdint>

// ---------------- problem constants ----------------
#define B_    8
#define CIN   128
#define COUT  128
#define NPTS  8192
#define KM    32
#define MODES 256
#define SPLIT1 16
#define KC    64          // K per chunk (fp32 elems)
#define NT_   128         // N tile
#define IGRP  8

// ---------------- device scratch ----------------
__device__ float g_part[SPLIT1 * B_ * CIN * MODES];   // 16.8 MB
__device__ float g_xhat[B_ * CIN * MODES];            // 1 MB
__device__ float g_W2[CIN * COUT * MODES];            // 16.8 MB
__device__ float g_part2[IGRP * B_ * COUT * MODES];   // 8.4 MB
__device__ float g_yhat[B_ * COUT * MODES];           // 1 MB

__device__ __forceinline__ uint32_t smem_u32(const void* p) {
    uint32_t a;
    asm("{ .reg .u64 t; cvta.to.shared.u64 t, %1; cvt.u32.u64 %0, t; }" : "=r"(a) : "l"(p));
    return a;
}
__device__ __forceinline__ uint32_t pk_bf16(float lo, float hi) {
    uint32_t r;
    asm("cvt.rn.bf16x2.f32 %0, %1, %2;" : "=r"(r) : "f"(hi), "f"(lo));
    return r;
}
// convert 8 consecutive fp32 to hi/lo bf16, store 16B each at hiA/loA
__device__ __forceinline__ void cvt_store8(uint32_t hiA, uint32_t loA, float4 v0, float4 v1) {
    uint32_t h0 = pk_bf16(v0.x, v0.y);
    uint32_t h1 = pk_bf16(v0.z, v0.w);
    uint32_t h2 = pk_bf16(v1.x, v1.y);
    uint32_t h3 = pk_bf16(v1.z, v1.w);
    float r0 = v0.x - __uint_as_float(h0 << 16);
    float r1 = v0.y - __uint_as_float(h0 & 0xffff0000u);
    float r2 = v0.z - __uint_as_float(h1 << 16);
    float r3 = v0.w - __uint_as_float(h1 & 0xffff0000u);
    float r4 = v1.x - __uint_as_float(h2 << 16);
    float r5 = v1.y - __uint_as_float(h2 & 0xffff0000u);
    float r6 = v1.z - __uint_as_float(h3 << 16);
    float r7 = v1.w - __uint_as_float(h3 & 0xffff0000u);
    uint32_t l0 = pk_bf16(r0, r1), l1 = pk_bf16(r2, r3);
    uint32_t l2 = pk_bf16(r4, r5), l3 = pk_bf16(r6, r7);
    asm volatile("st.shared.v4.b32 [%0], {%1,%2,%3,%4};" :: "r"(hiA), "r"(h0), "r"(h1), "r"(h2), "r"(h3));
    asm volatile("st.shared.v4.b32 [%0], {%1,%2,%3,%4};" :: "r"(loA), "r"(l0), "r"(l1), "r"(l2), "r"(l3));
}

#define LDSM4(r, addr) \
    asm volatile("ldmatrix.sync.aligned.m8n8.x4.shared.b16 {%0,%1,%2,%3}, [%4];" \
        : "=r"((r)[0]), "=r"((r)[1]), "=r"((r)[2]), "=r"((r)[3]) : "r"(addr))
#define LDSM4T(r, addr) \
    asm volatile("ldmatrix.sync.aligned.m8n8.x4.trans.shared.b16 {%0,%1,%2,%3}, [%4];" \
        : "=r"((r)[0]), "=r"((r)[1]), "=r"((r)[2]), "=r"((r)[3]) : "r"(addr))
#define MMA(c, a, bq) \
    asm volatile("mma.sync.aligned.m16n8k16.row.col.f32.bf16.bf16.f32 " \
        "{%0,%1,%2,%3}, {%4,%5,%6,%7}, {%8,%9}, {%0,%1,%2,%3};" \
        : "+f"((c)[0]), "+f"((c)[1]), "+f"((c)[2]), "+f"((c)[3]) \
        : "r"((a)[0]), "r"((a)[1]), "r"((a)[2]), "r"((a)[3]), "r"((bq)[0]), "r"((bq)[1]))

#define RSTR   144
#define ABYT   (128 * RSTR)                    // 18432 per half-tile

// ===========================================================================
// GEMM NT (stage 3): A rows and B rows K-contiguous. CTA 128x128, 256 thr,
// 8 warps (2m x 4n), warp tile 64x32, KC=64, SINGLE-buffered, 2 CTAs/SM.
// ===========================================================================
#define NT_OFF_AH 0
#define NT_OFF_AL (ABYT)
#define NT_OFF_BH (2 * ABYT)
#define NT_OFF_BL (3 * ABYT)
#define NT_SMEM   (4 * ABYT)                   // 73728

__global__ __launch_bounds__(256, 2) void gemm_nt(
    const float* __restrict__ A, const float* __restrict__ B, float* __restrict__ C,
    int lda, int ldb, int ldc,
    long sA, long sB, long sCb, int nChunks)
{
    extern __shared__ __align__(16) char smem[];
    const uint32_t sb = smem_u32(smem);
    const int tid = threadIdx.x, wid = tid >> 5, lane = tid & 31;
    const int nt = blockIdx.x, b = blockIdx.z;

    const float* Ab = A + (long)b * sA;
    const float* Bb = B + (long)b * sB + (long)nt * NT_ * ldb;
    float* Cb = C + (long)b * sCb + (long)nt * NT_;

    // staging: 4 thr/row, rows srow and srow+64, 16 floats per row-segment
    const int srow = tid >> 2, sk = (tid & 3) * 16;
    const float* ag = Ab + (long)srow * lda + sk;
    const float* bg = Bb + (long)srow * ldb + sk;
    const uint32_t sOff = (uint32_t)(srow * RSTR + sk * 2);

    const int wm = wid >> 2, wn = wid & 3;          // 2m x 4n, warp tile 64x32
    const int l16 = lane & 15, lh = lane >> 4;
    const int bn = ((lane >> 4) & 1) * 8 + (lane & 7);
    const int bk = ((lane >> 3) & 1) * 8;

    float c[4][4][4];
#pragma unroll
    for (int i = 0; i < 4; i++)
#pragma unroll
        for (int j = 0; j < 4; j++)
#pragma unroll
            for (int q = 0; q < 4; q++) c[i][j][q] = 0.f;

    for (int i = 0; i < nChunks; i++) {
        if (i) __syncthreads();                      // compute of i-1 done
        {
            const float* ap = ag + (long)i * KC;
            const float* bp = bg + (long)i * KC;
#pragma unroll
            for (int rb = 0; rb < 2; rb++) {         // rows srow, srow+64
                const float* ar = ap + (long)rb * 64 * lda;
                const float* br = bp + (long)rb * 64 * ldb;
                const uint32_t ro = sOff + rb * 64 * RSTR;
                float4 a0 = *(const float4*)(ar),     a1 = *(const float4*)(ar + 4);
                float4 a2 = *(const float4*)(ar + 8), a3 = *(const float4*)(ar + 12);
                float4 b0 = *(const float4*)(br),     b1 = *(const float4*)(br + 4);
                float4 b2 = *(const float4*)(br + 8), b3 = *(const float4*)(br + 12);
                cvt_store8(sb + NT_OFF_AH + ro,      sb + NT_OFF_AL + ro,      a0, a1);
                cvt_store8(sb + NT_OFF_AH + ro + 16, sb + NT_OFF_AL + ro + 16, a2, a3);
                cvt_store8(sb + NT_OFF_BH + ro,      sb + NT_OFF_BL + ro,      b0, b1);
                cvt_store8(sb + NT_OFF_BH + ro + 16, sb + NT_OFF_BL + ro + 16, b2, b3);
            }
        }
        __syncthreads();
#pragma unroll
        for (int h = 0; h < 4; h++) {
            uint32_t ahi[16], bhi[8], t[16];
            const uint32_t aA = sb + NT_OFF_AH + (uint32_t)((wm * 64 + l16) * RSTR + (h * 16 + lh * 8) * 2);
            const uint32_t bA = sb + NT_OFF_BH + (uint32_t)((wn * 32 + bn) * RSTR + (h * 16 + bk) * 2);
            LDSM4(&ahi[0], aA);
            LDSM4(&ahi[4], aA + 16 * RSTR);
            LDSM4(&ahi[8], aA + 32 * RSTR);
            LDSM4(&ahi[12], aA + 48 * RSTR);
            LDSM4(&bhi[0], bA);
            LDSM4(&bhi[4], bA + 16 * RSTR);
#pragma unroll
            for (int mt = 0; mt < 4; mt++)
#pragma unroll
                for (int nn = 0; nn < 4; nn++)
                    MMA(c[mt][nn], &ahi[mt * 4], &bhi[nn * 2]);
            LDSM4(&t[0], aA + ABYT);                 // alo
            LDSM4(&t[4], aA + ABYT + 16 * RSTR);
            LDSM4(&t[8], aA + ABYT + 32 * RSTR);
            LDSM4(&t[12], aA + ABYT + 48 * RSTR);
#pragma unroll
            for (int mt = 0; mt < 4; mt++)
#pragma unroll
                for (int nn = 0; nn < 4; nn++)
                    MMA(c[mt][nn], &t[mt * 4], &bhi[nn * 2]);
            LDSM4(&t[0], bA + ABYT);                 // blo (reuse t)
            LDSM4(&t[4], bA + ABYT + 16 * RSTR);
#pragma unroll
            for (int mt = 0; mt < 4; mt++)
#pragma unroll
                for (int nn = 0; nn < 4; nn++)
                    MMA(c[mt][nn], &ahi[mt * 4], &t[nn * 2]);
        }
    }

    const int mr = lane >> 2, ncol = wn * 32 + (lane & 3) * 2;
#pragma unroll
    for (int mt = 0; mt < 4; mt++)
#pragma unroll
        for (int nn = 0; nn < 4; nn++) {
            float* p = Cb + (long)(wm * 64 + mt * 16 + mr) * ldc + ncol + nn * 8;
            *(float2*)p = make_float2(c[mt][nn][0], c[mt][nn][1]);
            *(float2*)(p + (long)8 * ldc) = make_float2(c[mt][nn][2], c[mt][nn][3]);
        }
}

// ===========================================================================
// GEMM TB (stage 1): A rows K-contiguous; B = wbases [k][modes], trans frags.
// Same 256-thread / 64x32 warp-tile / single-buffer / 2 CTAs/SM structure.
// ===========================================================================
#define BRSTR  272
#define TB_BBYT (KC * BRSTR)                    // 17408 per half
#define TB_OFF_AH 0
#define TB_OFF_AL (ABYT)
#define TB_OFF_BH (2 * ABYT)
#define TB_OFF_BL (2 * ABYT + TB_BBYT)
#define TB_SMEM   (2 * ABYT + 2 * TB_BBYT)      // 71680

__global__ __launch_bounds__(256, 2) void gemm_tb(
    const float* __restrict__ A, const float* __restrict__ B, float* __restrict__ C,
    int nChunks)
{
    extern __shared__ __align__(16) char smem[];
    const uint32_t sb = smem_u32(smem);
    const int tid = threadIdx.x, wid = tid >> 5, lane = tid & 31;
    const int nt = blockIdx.x, sp = blockIdx.y, b = blockIdx.z;
    const long k0 = (long)sp * nChunks * KC;

    const float* Ab = A + (long)b * CIN * NPTS + k0;
    const float* Bb = B + (long)b * NPTS * MODES + k0 * MODES + nt * NT_;
    float* Cb = C + ((long)sp * B_ + b) * CIN * MODES + nt * NT_;

    const int srow = tid >> 2, sk = (tid & 3) * 16;
    const float* ag = Ab + (long)srow * NPTS + sk;
    const uint32_t aOff = (uint32_t)(srow * RSTR + sk * 2);
    const int brow = tid >> 4, bc = (tid & 15) * 8;
    const float* bg = Bb + (long)brow * MODES + bc;
    const uint32_t bOff = (uint32_t)(brow * BRSTR + bc * 2);

    const int wm = wid >> 2, wn = wid & 3;
    const int l16 = lane & 15, lh = lane >> 4;
    const int tkl = ((lane >> 3) & 1) * 8 + (lane & 7);
    const int tnl = (lane >> 4) * 8;

    float c[4][4][4];
#pragma unroll
    for (int i = 0; i < 4; i++)
#pragma unroll
        for (int j = 0; j < 4; j++)
#pragma unroll
            for (int q = 0; q < 4; q++) c[i][j][q] = 0.f;

    for (int i = 0; i < nChunks; i++) {
        if (i) __syncthreads();
        {
            const float* ap = ag + (long)i * KC;
#pragma unroll
            for (int rb = 0; rb < 2; rb++) {
                const float* ar = ap + (long)rb * 64 * NPTS;
                const uint32_t ro = aOff + rb * 64 * RSTR;
                float4 a0 = *(const float4*)(ar),     a1 = *(const float4*)(ar + 4);
                float4 a2 = *(const float4*)(ar + 8), a3 = *(const float4*)(ar + 12);
                cvt_store8(sb + TB_OFF_AH + ro,      sb + TB_OFF_AL + ro,      a0, a1);
                cvt_store8(sb + TB_OFF_AH + ro + 16, sb + TB_OFF_AL + ro + 16, a2, a3);
            }
            const float* bp = bg + (long)i * KC * MODES;
#pragma unroll
            for (int s = 0; s < 4; s++) {            // k-rows brow + 16s
                const float* br = bp + (long)s * 16 * MODES;
                const uint32_t ro = bOff + s * 16 * BRSTR;
                float4 b0 = *(const float4*)(br), b1 = *(const float4*)(br + 4);
                cvt_store8(sb + TB_OFF_BH + ro, sb + TB_OFF_BL + ro, b0, b1);
            }
        }
        __syncthreads();
#pragma unroll
        for (int h = 0; h < 4; h++) {
            uint32_t ahi[16], bhi[8], t[16];
            const uint32_t aA = sb + TB_OFF_AH + (uint32_t)((wm * 64 + l16) * RSTR + (h * 16 + lh * 8) * 2);
            const uint32_t bA = sb + TB_OFF_BH + (uint32_t)((h * 16 + tkl) * BRSTR + (wn * 32 + tnl) * 2);
            LDSM4(&ahi[0], aA);
            LDSM4(&ahi[4], aA + 16 * RSTR);
            LDSM4(&ahi[8], aA + 32 * RSTR);
            LDSM4(&ahi[12], aA + 48 * RSTR);
            LDSM4T(&bhi[0], bA);
            LDSM4T(&bhi[4], bA + 16 * 2);
#pragma unroll
            for (int mt = 0; mt < 4; mt++)
#pragma unroll
                for (int nn = 0; nn < 4; nn++)
                    MMA(c[mt][nn], &ahi[mt * 4], &bhi[nn * 2]);
            LDSM4(&t[0], aA + ABYT);
            LDSM4(&t[4], aA + ABYT + 16 * RSTR);
            LDSM4(&t[8], aA + ABYT + 32 * RSTR);
            LDSM4(&t[12], aA + ABYT + 48 * RSTR);
#pragma unroll
            for (int mt = 0; mt < 4; mt++)
#pragma unroll
                for (int nn = 0; nn < 4; nn++)
                    MMA(c[mt][nn], &t[mt * 4], &bhi[nn * 2]);
            LDSM4T(&t[0], bA + TB_BBYT);
            LDSM4T(&t[4], bA + TB_BBYT + 16 * 2);
#pragma unroll
            for (int mt = 0; mt < 4; mt++)
#pragma unroll
                for (int nn = 0; nn < 4; nn++)
                    MMA(c[mt][nn], &ahi[mt * 4], &t[nn * 2]);
        }
    }

    const int mr = lane >> 2, ncol = wn * 32 + (lane & 3) * 2;
#pragma unroll
    for (int mt = 0; mt < 4; mt++)
#pragma unroll
        for (int nn = 0; nn < 4; nn++) {
            float* p = Cb + (long)(wm * 64 + mt * 16 + mr) * MODES + ncol + nn * 8;
            *(float2*)p = make_float2(c[mt][nn][0], c[mt][nn][1]);
            *(float2*)(p + (long)8 * MODES) = make_float2(c[mt][nn][2], c[mt][nn][3]);
        }
}

// W2[r,k] = sum_j weights[r,j] * D[j,k]
__global__ __launch_bounds__(256) void k2a_w2(const float* __restrict__ weights,
                                              const float* __restrict__ D) {
    __shared__ float ws[64][KM];
    const int r0 = blockIdx.x * 64;
    const int k  = threadIdx.x;
    for (int idx = threadIdx.x; idx < 64 * KM; idx += 256)
        ws[idx >> 5][idx & 31] = weights[(size_t)r0 * KM + idx];
    float Dreg[KM];
#pragma unroll
    for (int j = 0; j < KM; j++) Dreg[j] = D[(size_t)j * MODES + k];
    __syncthreads();
    for (int r = 0; r < 64; r++) {
        float acc = 0.f;
#pragma unroll
        for (int j = 0; j < KM; j++) acc += ws[r][j] * Dreg[j];
        g_W2[(size_t)(r0 + r) * MODES + k] = acc;
    }
}

// split-K reduce: x_hat = sum over SPLIT1 partials (float4, coalesced)
__global__ __launch_bounds__(256) void k1_reduce() {
    const int i = blockIdx.x * 256 + threadIdx.x;
    const float4* p = (const float4*)g_part;
    float4 s = p[i];
#pragma unroll
    for (int q = 1; q < SPLIT1; q++) {
        float4 v = p[(size_t)q * (B_ * CIN * MODES / 4) + i];
        s.x += v.x; s.y += v.y; s.z += v.z; s.w += v.w;
    }
    ((float4*)g_xhat)[i] = s;
}

// Stage-2 partial: grid (32 o-tiles, IGRP, 4 b-pairs)
__global__ __launch_bounds__(256) void k2b_part() {
    const int o0 = blockIdx.x * 4;
    const int g  = blockIdx.y;
    const int b0 = blockIdx.z * 2;
    const int k  = threadIdx.x;
    float acc[2][4];
#pragma unroll
    for (int b = 0; b < 2; b++)
#pragma unroll
        for (int oo = 0; oo < 4; oo++) acc[b][oo] = 0.f;
    const int i0 = g * (CIN / IGRP);
#pragma unroll
    for (int ii = 0; ii < CIN / IGRP; ii++) {
        const int i = i0 + ii;
        float w[4];
#pragma unroll
        for (int oo = 0; oo < 4; oo++)
            w[oo] = g_W2[((size_t)i * COUT + o0 + oo) * MODES + k];
#pragma unroll
        for (int b = 0; b < 2; b++) {
            const float xv = g_xhat[((size_t)(b0 + b) * CIN + i) * MODES + k];
#pragma unroll
            for (int oo = 0; oo < 4; oo++) acc[b][oo] += xv * w[oo];
        }
    }
#pragma unroll
    for (int b = 0; b < 2; b++)
#pragma unroll
        for (int oo = 0; oo < 4; oo++)
            g_part2[(((size_t)g * B_ + b0 + b) * COUT + o0 + oo) * MODES + k] = acc[b][oo];
}

// Final stage-2 reduce
__global__ __launch_bounds__(256) void k2b_red2() {
    const int i = blockIdx.x * 256 + threadIdx.x;
    const float4* p = (const float4*)g_part2;
    float4 s = p[i];
#pragma unroll
    for (int q = 1; q < IGRP; q++) {
        float4 v = p[(size_t)q * (B_ * COUT * MODES / 4) + i];
        s.x += v.x; s.y += v.y; s.z += v.z; s.w += v.w;
    }
    ((float4*)g_yhat)[i] = s;
}

// ---------------------------------------------------------------------------
extern "C" void kernel_launch(void* const* d_in, const int* in_sizes, int n_in,
                              void* d_out, int out_size) {
    const float* x       = (const float*)d_in[0];   // (8, 128, 8192)
    const float* wbases  = (const float*)d_in[1];   // (8, 8192, 256)
    const float* bases   = (const float*)d_in[2];   // (8, 8192, 256)
    const float* weights = (const float*)d_in[3];   // (128, 128, 32)
    const float* Dm      = (const float*)d_in[4];   // (32, 256)
    float* y = (float*)d_out;                       // (8, 128, 8192)

    cudaFuncSetAttribute(gemm_nt, cudaFuncAttributeMaxDynamicSharedMemorySize, NT_SMEM);
    cudaFuncSetAttribute(gemm_tb, cudaFuncAttributeMaxDynamicSharedMemorySize, TB_SMEM);

    void *p_part, *p_yhat;
    cudaGetSymbolAddress(&p_part, g_part);
    cudaGetSymbolAddress(&p_yhat, g_yhat);

    // (1) W2 precompute
    k2a_w2<<<CIN * COUT / 64, 256>>>(weights, Dm);

    // (2) Stage 1: x_hat partials = x @ wbases  (256 CTAs, 2/SM)
    gemm_tb<<<dim3(MODES / NT_, SPLIT1, B_), 256, TB_SMEM>>>(
        x, wbases, (float*)p_part, (NPTS / SPLIT1) / KC);   // 8 chunks

    // (3) split-K reduce
    k1_reduce<<<(B_ * CIN * MODES / 4) / 256, 256>>>();

    // (4) stage-2 partials
    k2b_part<<<dim3(COUT / 4, IGRP, 4), 256>>>();

    // (5) stage-2 final reduce
    k2b_red2<<<(B_ * COUT * MODES / 4) / 256, 256>>>();

    // (6) Stage 3: y = y_hat @ bases^T  (512 CTAs, 2/SM)
    gemm_nt<<<dim3(NPTS / NT_, 1, B_), 256, NT_SMEM>>>(
        (const float*)p_yhat, bases, y,
        MODES, MODES, NPTS,
        (long)COUT * MODES, (long)NPTS * MODES, (long)CIN * NPTS,
        MODES / KC);                                        // 4 chunks
}

// round 11
// speedup vs baseline: 1.3118x; 1.0905x over previous
#include <cuda_runtime.h>
#include <cstdint>

// ---------------- problem constants ----------------
#define B_    8
#define CIN   128
#define COUT  128
#define NPTS  8192
#define KM    32
#define MODES 256
#define SPLIT1 16
#define KC    64          // K per chunk (fp32 elems)
#define NT_   128         // N tile
#define IGRP  8

// ---------------- device scratch ----------------
__device__ float g_part[SPLIT1 * B_ * CIN * MODES];   // 16.8 MB
__device__ float g_xhat[B_ * CIN * MODES];            // 1 MB
__device__ float g_W2[CIN * COUT * MODES];            // 16.8 MB
__device__ float g_part2[IGRP * B_ * COUT * MODES];   // 8.4 MB
__device__ float g_yhat[B_ * COUT * MODES];           // 1 MB

__device__ __forceinline__ uint32_t smem_u32(const void* p) {
    uint32_t a;
    asm("{ .reg .u64 t; cvta.to.shared.u64 t, %1; cvt.u32.u64 %0, t; }" : "=r"(a) : "l"(p));
    return a;
}
// pack: low 16 = f16(lo_arg), high 16 = f16(hi_arg)
__device__ __forceinline__ uint32_t pk_f16(float lo, float hi) {
    uint32_t r;
    asm("cvt.rn.f16x2.f32 %0, %1, %2;" : "=r"(r) : "f"(hi), "f"(lo));
    return r;
}
// unpack f16x2 -> two fp32
__device__ __forceinline__ void up_f16(uint32_t h, float& a, float& b) {
    asm("{ .reg .f16 x, y; mov.b32 {x, y}, %2; cvt.f32.f16 %0, x; cvt.f32.f16 %1, y; }"
        : "=f"(a), "=f"(b) : "r"(h));
}
// A-operand: 8 fp32 -> hi fp16 (16B at hiA) + residual-lo fp16 (16B at loA)
__device__ __forceinline__ void cvt_storeA8(uint32_t hiA, uint32_t loA, float4 v0, float4 v1) {
    uint32_t h0 = pk_f16(v0.x, v0.y);
    uint32_t h1 = pk_f16(v0.z, v0.w);
    uint32_t h2 = pk_f16(v1.x, v1.y);
    uint32_t h3 = pk_f16(v1.z, v1.w);
    float f0, f1, f2, f3, f4, f5, f6, f7;
    up_f16(h0, f0, f1);
    up_f16(h1, f2, f3);
    up_f16(h2, f4, f5);
    up_f16(h3, f6, f7);
    uint32_t l0 = pk_f16(v0.x - f0, v0.y - f1);
    uint32_t l1 = pk_f16(v0.z - f2, v0.w - f3);
    uint32_t l2 = pk_f16(v1.x - f4, v1.y - f5);
    uint32_t l3 = pk_f16(v1.z - f6, v1.w - f7);
    asm volatile("st.shared.v4.b32 [%0], {%1,%2,%3,%4};" :: "r"(hiA), "r"(h0), "r"(h1), "r"(h2), "r"(h3));
    asm volatile("st.shared.v4.b32 [%0], {%1,%2,%3,%4};" :: "r"(loA), "r"(l0), "r"(l1), "r"(l2), "r"(l3));
}
// B-operand: 8 fp32 -> 8 fp16 (16B)
__device__ __forceinline__ void cvt_storeB8(uint32_t dst, float4 v0, float4 v1) {
    uint32_t h0 = pk_f16(v0.x, v0.y);
    uint32_t h1 = pk_f16(v0.z, v0.w);
    uint32_t h2 = pk_f16(v1.x, v1.y);
    uint32_t h3 = pk_f16(v1.z, v1.w);
    asm volatile("st.shared.v4.b32 [%0], {%1,%2,%3,%4};" :: "r"(dst), "r"(h0), "r"(h1), "r"(h2), "r"(h3));
}

#define LDSM4(r, addr) \
    asm volatile("ldmatrix.sync.aligned.m8n8.x4.shared.b16 {%0,%1,%2,%3}, [%4];" \
        : "=r"((r)[0]), "=r"((r)[1]), "=r"((r)[2]), "=r"((r)[3]) : "r"(addr))
#define LDSM4T(r, addr) \
    asm volatile("ldmatrix.sync.aligned.m8n8.x4.trans.shared.b16 {%0,%1,%2,%3}, [%4];" \
        : "=r"((r)[0]), "=r"((r)[1]), "=r"((r)[2]), "=r"((r)[3]) : "r"(addr))
#define MMA(c, a, bq) \
    asm volatile("mma.sync.aligned.m16n8k16.row.col.f32.f16.f16.f32 " \
        "{%0,%1,%2,%3}, {%4,%5,%6,%7}, {%8,%9}, {%0,%1,%2,%3};" \
        : "+f"((c)[0]), "+f"((c)[1]), "+f"((c)[2]), "+f"((c)[3]) \
        : "r"((a)[0]), "r"((a)[1]), "r"((a)[2]), "r"((a)[3]), "r"((bq)[0]), "r"((bq)[1]))

#define RSTR   144
#define ABYT   (128 * RSTR)                    // 18432 per tile half

// ===========================================================================
// GEMM NT (stage 3): A/B rows K-contiguous. CTA 128x128, 256 thr, 8 warps
// (4m x 2n), warp tile 32x64, KC=64, single-buffered, 2 CTAs/SM. fp16x2.
// ===========================================================================
#define NT_OFF_AH 0
#define NT_OFF_AL (ABYT)
#define NT_OFF_BH (2 * ABYT)
#define NT_SMEM   (3 * ABYT)                   // 55296

__global__ __launch_bounds__(256, 2) void gemm_nt(
    const float* __restrict__ A, const float* __restrict__ B, float* __restrict__ C,
    int lda, int ldb, int ldc,
    long sA, long sB, long sCb, int nChunks)
{
    extern __shared__ __align__(16) char smem[];
    const uint32_t sb = smem_u32(smem);
    const int tid = threadIdx.x, wid = tid >> 5, lane = tid & 31;
    const int nt = blockIdx.x, b = blockIdx.z;

    const float* Ab = A + (long)b * sA;
    const float* Bb = B + (long)b * sB + (long)nt * NT_ * ldb;
    float* Cb = C + (long)b * sCb + (long)nt * NT_;

    const int srow = tid >> 2, sk = (tid & 3) * 16;
    const float* ag = Ab + (long)srow * lda + sk;
    const float* bg = Bb + (long)srow * ldb + sk;
    const uint32_t sOff = (uint32_t)(srow * RSTR + sk * 2);

    const int wm = wid >> 1, wn = wid & 1;          // 4m x 2n, warp tile 32x64
    const int l16 = lane & 15, lh = lane >> 4;
    const int bn = ((lane >> 4) & 1) * 8 + (lane & 7);
    const int bk = ((lane >> 3) & 1) * 8;

    float c[2][8][4];
#pragma unroll
    for (int i = 0; i < 2; i++)
#pragma unroll
        for (int j = 0; j < 8; j++)
#pragma unroll
            for (int q = 0; q < 4; q++) c[i][j][q] = 0.f;

    for (int i = 0; i < nChunks; i++) {
        if (i) __syncthreads();
        {
            const float* ap = ag + (long)i * KC;
            const float* bp = bg + (long)i * KC;
#pragma unroll
            for (int rb = 0; rb < 2; rb++) {
                const float* ar = ap + (long)rb * 64 * lda;
                const float* br = bp + (long)rb * 64 * ldb;
                const uint32_t ro = sOff + rb * 64 * RSTR;
                float4 a0 = *(const float4*)(ar),     a1 = *(const float4*)(ar + 4);
                float4 a2 = *(const float4*)(ar + 8), a3 = *(const float4*)(ar + 12);
                float4 b0 = *(const float4*)(br),     b1 = *(const float4*)(br + 4);
                float4 b2 = *(const float4*)(br + 8), b3 = *(const float4*)(br + 12);
                cvt_storeA8(sb + NT_OFF_AH + ro,      sb + NT_OFF_AL + ro,      a0, a1);
                cvt_storeA8(sb + NT_OFF_AH + ro + 16, sb + NT_OFF_AL + ro + 16, a2, a3);
                cvt_storeB8(sb + NT_OFF_BH + ro,      b0, b1);
                cvt_storeB8(sb + NT_OFF_BH + ro + 16, b2, b3);
            }
        }
        __syncthreads();
#pragma unroll
        for (int h = 0; h < 4; h++) {
            uint32_t ahi[8], alo[8], bh[16];
            const uint32_t aA = sb + NT_OFF_AH + (uint32_t)((wm * 32 + l16) * RSTR + (h * 16 + lh * 8) * 2);
            const uint32_t bA = sb + NT_OFF_BH + (uint32_t)((wn * 64 + bn) * RSTR + (h * 16 + bk) * 2);
            LDSM4(&ahi[0], aA);
            LDSM4(&ahi[4], aA + 16 * RSTR);
            LDSM4(&bh[0], bA);
            LDSM4(&bh[4], bA + 16 * RSTR);
            LDSM4(&bh[8], bA + 32 * RSTR);
            LDSM4(&bh[12], bA + 48 * RSTR);
#pragma unroll
            for (int mt = 0; mt < 2; mt++)
#pragma unroll
                for (int nn = 0; nn < 8; nn++)
                    MMA(c[mt][nn], &ahi[mt * 4], &bh[nn * 2]);
            LDSM4(&alo[0], aA + ABYT);
            LDSM4(&alo[4], aA + ABYT + 16 * RSTR);
#pragma unroll
            for (int mt = 0; mt < 2; mt++)
#pragma unroll
                for (int nn = 0; nn < 8; nn++)
                    MMA(c[mt][nn], &alo[mt * 4], &bh[nn * 2]);
        }
    }

    const int mr = lane >> 2, nc0 = wn * 64 + (lane & 3) * 2;
#pragma unroll
    for (int mt = 0; mt < 2; mt++)
#pragma unroll
        for (int nn = 0; nn < 8; nn++) {
            float* p = Cb + (long)(wm * 32 + mt * 16 + mr) * ldc + nc0 + nn * 8;
            *(float2*)p = make_float2(c[mt][nn][0], c[mt][nn][1]);
            *(float2*)(p + (long)8 * ldc) = make_float2(c[mt][nn][2], c[mt][nn][3]);
        }
}

// ===========================================================================
// GEMM TB (stage 1): A rows K-contiguous; B = wbases [k][modes], trans frags.
// Same fp16x2 structure: 4m x 2n warps, warp tile 32x64.
// ===========================================================================
#define BRSTR  272
#define TB_BBYT (KC * BRSTR)                    // 17408
#define TB_OFF_AH 0
#define TB_OFF_AL (ABYT)
#define TB_OFF_BH (2 * ABYT)
#define TB_SMEM   (2 * ABYT + TB_BBYT)          // 54272

__global__ __launch_bounds__(256, 2) void gemm_tb(
    const float* __restrict__ A, const float* __restrict__ B, float* __restrict__ C,
    int nChunks)
{
    extern __shared__ __align__(16) char smem[];
    const uint32_t sb = smem_u32(smem);
    const int tid = threadIdx.x, wid = tid >> 5, lane = tid & 31;
    const int nt = blockIdx.x, sp = blockIdx.y, b = blockIdx.z;
    const long k0 = (long)sp * nChunks * KC;

    const float* Ab = A + (long)b * CIN * NPTS + k0;
    const float* Bb = B + (long)b * NPTS * MODES + k0 * MODES + nt * NT_;
    float* Cb = C + ((long)sp * B_ + b) * CIN * MODES + nt * NT_;

    const int srow = tid >> 2, sk = (tid & 3) * 16;
    const float* ag = Ab + (long)srow * NPTS + sk;
    const uint32_t aOff = (uint32_t)(srow * RSTR + sk * 2);
    const int brow = tid >> 4, bc = (tid & 15) * 8;
    const float* bg = Bb + (long)brow * MODES + bc;
    const uint32_t bOff = (uint32_t)(brow * BRSTR + bc * 2);

    const int wm = wid >> 1, wn = wid & 1;
    const int l16 = lane & 15, lh = lane >> 4;
    const int tkl = ((lane >> 3) & 1) * 8 + (lane & 7);
    const int tnl = (lane >> 4) * 8;

    float c[2][8][4];
#pragma unroll
    for (int i = 0; i < 2; i++)
#pragma unroll
        for (int j = 0; j < 8; j++)
#pragma unroll
            for (int q = 0; q < 4; q++) c[i][j][q] = 0.f;

    for (int i = 0; i < nChunks; i++) {
        if (i) __syncthreads();
        {
            const float* ap = ag + (long)i * KC;
#pragma unroll
            for (int rb = 0; rb < 2; rb++) {
                const float* ar = ap + (long)rb * 64 * NPTS;
                const uint32_t ro = aOff + rb * 64 * RSTR;
                float4 a0 = *(const float4*)(ar),     a1 = *(const float4*)(ar + 4);
                float4 a2 = *(const float4*)(ar + 8), a3 = *(const float4*)(ar + 12);
                cvt_storeA8(sb + TB_OFF_AH + ro,      sb + TB_OFF_AL + ro,      a0, a1);
                cvt_storeA8(sb + TB_OFF_AH + ro + 16, sb + TB_OFF_AL + ro + 16, a2, a3);
            }
            const float* bp = bg + (long)i * KC * MODES;
#pragma unroll
            for (int s = 0; s < 4; s++) {            // k-rows brow + 16s
                const float* br = bp + (long)s * 16 * MODES;
                const uint32_t ro = bOff + s * 16 * BRSTR;
                float4 b0 = *(const float4*)(br), b1 = *(const float4*)(br + 4);
                cvt_storeB8(sb + TB_OFF_BH + ro, b0, b1);
            }
        }
        __syncthreads();
#pragma unroll
        for (int h = 0; h < 4; h++) {
            uint32_t ahi[8], alo[8], bh[16];
            const uint32_t aA = sb + TB_OFF_AH + (uint32_t)((wm * 32 + l16) * RSTR + (h * 16 + lh * 8) * 2);
            const uint32_t bA = sb + TB_OFF_BH + (uint32_t)((h * 16 + tkl) * BRSTR + (wn * 64 + tnl) * 2);
            LDSM4(&ahi[0], aA);
            LDSM4(&ahi[4], aA + 16 * RSTR);
            LDSM4T(&bh[0], bA);
            LDSM4T(&bh[4], bA + 16 * 2);
            LDSM4T(&bh[8], bA + 32 * 2);
            LDSM4T(&bh[12], bA + 48 * 2);
#pragma unroll
            for (int mt = 0; mt < 2; mt++)
#pragma unroll
                for (int nn = 0; nn < 8; nn++)
                    MMA(c[mt][nn], &ahi[mt * 4], &bh[nn * 2]);
            LDSM4(&alo[0], aA + ABYT);
            LDSM4(&alo[4], aA + ABYT + 16 * RSTR);
#pragma unroll
            for (int mt = 0; mt < 2; mt++)
#pragma unroll
                for (int nn = 0; nn < 8; nn++)
                    MMA(c[mt][nn], &alo[mt * 4], &bh[nn * 2]);
        }
    }

    const int mr = lane >> 2, nc0 = wn * 64 + (lane & 3) * 2;
#pragma unroll
    for (int mt = 0; mt < 2; mt++)
#pragma unroll
        for (int nn = 0; nn < 8; nn++) {
            float* p = Cb + (long)(wm * 32 + mt * 16 + mr) * MODES + nc0 + nn * 8;
            *(float2*)p = make_float2(c[mt][nn][0], c[mt][nn][1]);
            *(float2*)(p + (long)8 * MODES) = make_float2(c[mt][nn][2], c[mt][nn][3]);
        }
}

// W2[r,k] = sum_j weights[r,j] * D[j,k]
__global__ __launch_bounds__(256) void k2a_w2(const float* __restrict__ weights,
                                              const float* __restrict__ D) {
    __shared__ float ws[64][KM];
    const int r0 = blockIdx.x * 64;
    const int k  = threadIdx.x;
    for (int idx = threadIdx.x; idx < 64 * KM; idx += 256)
        ws[idx >> 5][idx & 31] = weights[(size_t)r0 * KM + idx];
    float Dreg[KM];
#pragma unroll
    for (int j = 0; j < KM; j++) Dreg[j] = D[(size_t)j * MODES + k];
    __syncthreads();
    for (int r = 0; r < 64; r++) {
        float acc = 0.f;
#pragma unroll
        for (int j = 0; j < KM; j++) acc += ws[r][j] * Dreg[j];
        g_W2[(size_t)(r0 + r) * MODES + k] = acc;
    }
}

// split-K reduce: x_hat = sum over SPLIT1 partials (float4, coalesced)
__global__ __launch_bounds__(256) void k1_reduce() {
    const int i = blockIdx.x * 256 + threadIdx.x;
    const float4* p = (const float4*)g_part;
    float4 s = p[i];
#pragma unroll
    for (int q = 1; q < SPLIT1; q++) {
        float4 v = p[(size_t)q * (B_ * CIN * MODES / 4) + i];
        s.x += v.x; s.y += v.y; s.z += v.z; s.w += v.w;
    }
    ((float4*)g_xhat)[i] = s;
}

// Stage-2 partial: grid (32 o-tiles, IGRP, 4 b-pairs)
__global__ __launch_bounds__(256) void k2b_part() {
    const int o0 = blockIdx.x * 4;
    const int g  = blockIdx.y;
    const int b0 = blockIdx.z * 2;
    const int k  = threadIdx.x;
    float acc[2][4];
#pragma unroll
    for (int b = 0; b < 2; b++)
#pragma unroll
        for (int oo = 0; oo < 4; oo++) acc[b][oo] = 0.f;
    const int i0 = g * (CIN / IGRP);
#pragma unroll
    for (int ii = 0; ii < CIN / IGRP; ii++) {
        const int i = i0 + ii;
        float w[4];
#pragma unroll
        for (int oo = 0; oo < 4; oo++)
            w[oo] = g_W2[((size_t)i * COUT + o0 + oo) * MODES + k];
#pragma unroll
        for (int b = 0; b < 2; b++) {
            const float xv = g_xhat[((size_t)(b0 + b) * CIN + i) * MODES + k];
#pragma unroll
            for (int oo = 0; oo < 4; oo++) acc[b][oo] += xv * w[oo];
        }
    }
#pragma unroll
    for (int b = 0; b < 2; b++)
#pragma unroll
        for (int oo = 0; oo < 4; oo++)
            g_part2[(((size_t)g * B_ + b0 + b) * COUT + o0 + oo) * MODES + k] = acc[b][oo];
}

// Final stage-2 reduce
__global__ __launch_bounds__(256) void k2b_red2() {
    const int i = blockIdx.x * 256 + threadIdx.x;
    const float4* p = (const float4*)g_part2;
    float4 s = p[i];
#pragma unroll
    for (int q = 1; q < IGRP; q++) {
        float4 v = p[(size_t)q * (B_ * COUT * MODES / 4) + i];
        s.x += v.x; s.y += v.y; s.z += v.z; s.w += v.w;
    }
    ((float4*)g_yhat)[i] = s;
}

// ---------------------------------------------------------------------------
extern "C" void kernel_launch(void* const* d_in, const int* in_sizes, int n_in,
                              void* d_out, int out_size) {
    const float* x       = (const float*)d_in[0];   // (8, 128, 8192)
    const float* wbases  = (const float*)d_in[1];   // (8, 8192, 256)
    const float* bases   = (const float*)d_in[2];   // (8, 8192, 256)
    const float* weights = (const float*)d_in[3];   // (128, 128, 32)
    const float* Dm      = (const float*)d_in[4];   // (32, 256)
    float* y = (float*)d_out;                       // (8, 128, 8192)

    cudaFuncSetAttribute(gemm_nt, cudaFuncAttributeMaxDynamicSharedMemorySize, NT_SMEM);
    cudaFuncSetAttribute(gemm_tb, cudaFuncAttributeMaxDynamicSharedMemorySize, TB_SMEM);

    void *p_part, *p_yhat;
    cudaGetSymbolAddress(&p_part, g_part);
    cudaGetSymbolAddress(&p_yhat, g_yhat);

    // (1) W2 precompute
    k2a_w2<<<CIN * COUT / 64, 256>>>(weights, Dm);

    // (2) Stage 1: x_hat partials = x @ wbases  (256 CTAs, 2/SM)
    gemm_tb<<<dim3(MODES / NT_, SPLIT1, B_), 256, TB_SMEM>>>(
        x, wbases, (float*)p_part, (NPTS / SPLIT1) / KC);   // 8 chunks

    // (3) split-K reduce
    k1_reduce<<<(B_ * CIN * MODES / 4) / 256, 256>>>();

    // (4) stage-2 partials
    k2b_part<<<dim3(COUT / 4, IGRP, 4), 256>>>();

    // (5) stage-2 final reduce
    k2b_red2<<<(B_ * COUT * MODES / 4) / 256, 256>>>();

    // (6) Stage 3: y = y_hat @ bases^T  (512 CTAs, 2/SM)
    gemm_nt<<<dim3(NPTS / NT_, 1, B_), 256, NT_SMEM>>>(
        (const float*)p_yhat, bases, y,
        MODES, MODES, NPTS,
        (long)COUT * MODES, (long)NPTS * MODES, (long)CIN * NPTS,
        MODES / KC);                                        // 4 chunks
}